// round 4
// baseline (speedup 1.0000x reference)
#include <cuda_runtime.h>
#include <cuda_fp16.h>
#include <cuda_bf16.h>

#define N_NODES 100000
#define N_EDGES 1600000
#define IN_F 128
#define OUT_F 48
#define NBLK_SCAN ((N_NODES + 1023) / 1024)   // 98

// Scratch (__device__ globals; zero-initialized at load; no allocations allowed)
__device__ float  g_ssrc[N_NODES];                    // h . w_src
__device__ float  g_sdst[N_NODES];                    // h . w_dst
__device__ __half g_hh[(size_t)N_NODES * OUT_F];      // projected features (fp16)
__device__ int    g_cnt[N_NODES];                     // degree by dst (zero at entry!)
__device__ int    g_off[N_NODES];                     // CSR offsets
__device__ int    g_cursor[N_NODES];                  // scatter cursors
__device__ unsigned long long g_state[NBLK_SCAN];     // lookback state (zero at entry!)
__device__ unsigned long long g_edge[N_EDGES];        // packed {src, ex}

// ---------------------------------------------------------------------------
// GEMM + dst histogram.
// ---------------------------------------------------------------------------
__global__ void __launch_bounds__(128) k_gemm(
    const float* __restrict__ feat, const float* __restrict__ Ww,
    const float* __restrict__ Wb, const float* __restrict__ attnw,
    const int* __restrict__ dst)
{
    // --- histogram of dst (grid-stride, no-return atomics drain under FMAs) ---
    {
        int gsz = gridDim.x * 128;
        for (int e = blockIdx.x * 128 + threadIdx.x; e < N_EDGES; e += gsz)
            atomicAdd(&g_cnt[dst[e]], 1);
    }

    __shared__ unsigned long long sWp[IN_F][OUT_F / 2];
    __shared__ float sb[OUT_F], sws[OUT_F], swd[OUT_F];

    int tid = threadIdx.x;
    for (int i = tid; i < IN_F * (OUT_F / 2); i += 128) {
        int k  = i / (OUT_F / 2);
        int jj = i % (OUT_F / 2);
        float lo = Ww[(2 * jj) * IN_F + k];
        float hi = Ww[(2 * jj + 1) * IN_F + k];
        unsigned long long p;
        asm("mov.b64 %0, {%1, %2};" : "=l"(p) : "f"(lo), "f"(hi));
        sWp[k][jj] = p;
    }
    if (tid < OUT_F) {
        sb[tid]  = Wb[tid];
        sws[tid] = attnw[tid];
        swd[tid] = attnw[OUT_F + tid];
    }
    __syncthreads();

    long n0 = (long)blockIdx.x * 256 + tid;
    long n1 = n0 + 128;
    bool v0 = n0 < N_NODES, v1 = n1 < N_NODES;
    const float4* r0 = (const float4*)(feat + (v0 ? n0 : 0) * IN_F);
    const float4* r1 = (const float4*)(feat + (v1 ? n1 : 0) * IN_F);

    unsigned long long a0[OUT_F / 2], a1[OUT_F / 2];
#pragma unroll
    for (int jj = 0; jj < OUT_F / 2; jj++) {
        unsigned long long p;
        asm("mov.b64 %0, {%1, %2};" : "=l"(p) : "f"(sb[2 * jj]), "f"(sb[2 * jj + 1]));
        a0[jj] = p;
        a1[jj] = p;
    }

#pragma unroll 2
    for (int k4 = 0; k4 < IN_F / 4; k4++) {
        float4 f0 = r0[k4];
        float4 f1 = r1[k4];
        float fs0[4] = {f0.x, f0.y, f0.z, f0.w};
        float fs1[4] = {f1.x, f1.y, f1.z, f1.w};
#pragma unroll
        for (int u = 0; u < 4; u++) {
            unsigned long long ff0, ff1;
            asm("mov.b64 %0, {%1, %1};" : "=l"(ff0) : "f"(fs0[u]));
            asm("mov.b64 %0, {%1, %1};" : "=l"(ff1) : "f"(fs1[u]));
            int k = 4 * k4 + u;
#pragma unroll
            for (int jj = 0; jj < OUT_F / 2; jj++) {
                unsigned long long w = sWp[k][jj];
                asm("fma.rn.f32x2 %0, %1, %2, %0;" : "+l"(a0[jj]) : "l"(ff0), "l"(w));
                asm("fma.rn.f32x2 %0, %1, %2, %0;" : "+l"(a1[jj]) : "l"(ff1), "l"(w));
            }
        }
    }

    if (v0) {
        float s1 = 0.0f, s2 = 0.0f;
        unsigned hh[OUT_F / 2];
#pragma unroll
        for (int jj = 0; jj < OUT_F / 2; jj++) {
            float lo, hi;
            asm("mov.b64 {%0, %1}, %2;" : "=f"(lo), "=f"(hi) : "l"(a0[jj]));
            s1 += lo * sws[2 * jj] + hi * sws[2 * jj + 1];
            s2 += lo * swd[2 * jj] + hi * swd[2 * jj + 1];
            __half2 h2 = __floats2half2_rn(lo, hi);
            hh[jj] = *(unsigned*)&h2;
        }
        uint4* hr = (uint4*)(g_hh + (size_t)n0 * OUT_F);
#pragma unroll
        for (int i = 0; i < 6; i++)
            hr[i] = make_uint4(hh[4 * i], hh[4 * i + 1], hh[4 * i + 2], hh[4 * i + 3]);
        g_ssrc[n0] = s1;
        g_sdst[n0] = s2;
    }
    if (v1) {
        float s1 = 0.0f, s2 = 0.0f;
        unsigned hh[OUT_F / 2];
#pragma unroll
        for (int jj = 0; jj < OUT_F / 2; jj++) {
            float lo, hi;
            asm("mov.b64 {%0, %1}, %2;" : "=f"(lo), "=f"(hi) : "l"(a1[jj]));
            s1 += lo * sws[2 * jj] + hi * sws[2 * jj + 1];
            s2 += lo * swd[2 * jj] + hi * swd[2 * jj + 1];
            __half2 h2 = __floats2half2_rn(lo, hi);
            hh[jj] = *(unsigned*)&h2;
        }
        uint4* hr = (uint4*)(g_hh + (size_t)n1 * OUT_F);
#pragma unroll
        for (int i = 0; i < 6; i++)
            hr[i] = make_uint4(hh[4 * i], hh[4 * i + 1], hh[4 * i + 2], hh[4 * i + 3]);
        g_ssrc[n1] = s1;
        g_sdst[n1] = s2;
    }
}

// ---------------------------------------------------------------------------
// Single-pass exclusive scan of g_cnt -> g_off/g_cursor (decoupled lookback).
// ---------------------------------------------------------------------------
__global__ void __launch_bounds__(1024) k_scan()
{
    __shared__ int wsum[32];
    __shared__ int s_prefix;
    int tid = threadIdx.x, bid = blockIdx.x;
    int gid = bid * 1024 + tid;
    int lane = tid & 31, wid = tid >> 5;
    int x = (gid < N_NODES) ? g_cnt[gid] : 0;
    int incl = x;
#pragma unroll
    for (int o = 1; o < 32; o <<= 1) {
        int y = __shfl_up_sync(0xFFFFFFFFu, incl, o);
        if (lane >= o) incl += y;
    }
    if (lane == 31) wsum[wid] = incl;
    __syncthreads();
    if (wid == 0) {
        int v = wsum[lane];
#pragma unroll
        for (int o = 1; o < 32; o <<= 1) {
            int y = __shfl_up_sync(0xFFFFFFFFu, v, o);
            if (lane >= o) v += y;
        }
        wsum[lane] = v;
    }
    __syncthreads();
    int wofs = (wid > 0) ? wsum[wid - 1] : 0;
    int total = wsum[31];

    if (tid == 0) {
        if (bid == 0) {
            atomicExch(&g_state[0], (2ULL << 62) | (unsigned)total);
            s_prefix = 0;
        } else {
            atomicExch(&g_state[bid], (1ULL << 62) | (unsigned)total);
            int run = 0;
            int j = bid - 1;
            while (true) {
                unsigned long long v = atomicAdd(&g_state[j], 0ULL);
                unsigned f = (unsigned)(v >> 62);
                if (f == 0) { __nanosleep(20); continue; }
                run += (int)(v & 0xFFFFFFFFULL);
                if (f == 2) break;
                j--;
            }
            atomicExch(&g_state[bid], (2ULL << 62) | (unsigned)(run + total));
            s_prefix = run;
        }
    }
    __syncthreads();
    if (gid < N_NODES) {
        int o = s_prefix + wofs + incl - x;
        g_off[gid] = o;
        g_cursor[gid] = o;
    }
}

// ---------------------------------------------------------------------------
// Scatter: 2 edges/thread; ex = exp(leaky(s_src[s]+s_dst[d]+b));
// place {src,ex} at dst-sorted position.
// ---------------------------------------------------------------------------
__global__ void __launch_bounds__(256) k_scatter(
    const int* __restrict__ src, const int* __restrict__ dst,
    const float* __restrict__ attnb)
{
    int i = blockIdx.x * blockDim.x + threadIdx.x;
    int e0 = i * 2;
    if (e0 >= N_EDGES) return;
    float b = attnb[0];

    int2 s2 = *(const int2*)(src + e0);
    int2 d2 = *(const int2*)(dst + e0);

    float v0 = g_ssrc[s2.x] + g_sdst[d2.x] + b;
    float v1 = g_ssrc[s2.y] + g_sdst[d2.y] + b;
    v0 = (v0 > 0.0f) ? v0 : 0.2f * v0;
    v1 = (v1 > 0.0f) ? v1 : 0.2f * v1;
    float ex0 = __expf(v0);
    float ex1 = __expf(v1);

    int p0 = atomicAdd(&g_cursor[d2.x], 1);
    int p1 = atomicAdd(&g_cursor[d2.y], 1);
    g_edge[p0] = ((unsigned long long)(unsigned)s2.x << 32) | __float_as_uint(ex0);
    g_edge[p1] = ((unsigned long long)(unsigned)s2.y << 32) | __float_as_uint(ex1);
}

// ---------------------------------------------------------------------------
// Gather: 2 threads/node, 24 outputs each (3x uint4 fp16 loads per edge).
// 2-edge unroll for MLP. No atomics. Restores zero-invariants afterwards.
// ---------------------------------------------------------------------------
__device__ __forceinline__ void acc6(float* a, unsigned w0, unsigned w1, unsigned w2, float ex)
{
    float2 f;
    f = __half22float2(*(__half2*)&w0); a[0] = fmaf(f.x, ex, a[0]); a[1] = fmaf(f.y, ex, a[1]);
    f = __half22float2(*(__half2*)&w1); a[2] = fmaf(f.x, ex, a[2]); a[3] = fmaf(f.y, ex, a[3]);
    f = __half22float2(*(__half2*)&w2); a[4] = fmaf(f.x, ex, a[4]); a[5] = fmaf(f.y, ex, a[5]);
}

__global__ void __launch_bounds__(256) k_gather(float* __restrict__ out)
{
    int gt = blockIdx.x * blockDim.x + threadIdx.x;
    int n = gt >> 1;
    int t = gt & 1;
    if (n >= N_NODES) return;
    int start = g_off[n];
    int deg = g_cnt[n];

    const uint4* H = (const uint4*)g_hh;  // row = 6 uint4 (96B)
    int hb = t * 3;                       // uint4 index within row

    float acc[24];
#pragma unroll
    for (int i = 0; i < 24; i++) acc[i] = 0.0f;
    float den = 0.0f;

    int k = 0;
    for (; k + 2 <= deg; k += 2) {
        unsigned long long p0 = g_edge[start + k];
        unsigned long long p1 = g_edge[start + k + 1];
        float ex0 = __uint_as_float((unsigned)p0);
        float ex1 = __uint_as_float((unsigned)p1);
        int s0 = (int)(p0 >> 32), s1 = (int)(p1 >> 32);
        const uint4* h0 = H + s0 * 6 + hb;
        const uint4* h1 = H + s1 * 6 + hb;
        uint4 w00 = h0[0], w01 = h0[1], w02 = h0[2];
        uint4 w10 = h1[0], w11 = h1[1], w12 = h1[2];
        den += ex0 + ex1;
        acc6(acc +  0, w00.x, w00.y, w00.z, ex0); acc6(acc +  6, w00.w, w01.x, w01.y, ex0);
        acc6(acc + 12, w01.z, w01.w, w02.x, ex0); acc6(acc + 18, w02.y, w02.z, w02.w, ex0);
        acc6(acc +  0, w10.x, w10.y, w10.z, ex1); acc6(acc +  6, w10.w, w11.x, w11.y, ex1);
        acc6(acc + 12, w11.z, w11.w, w12.x, ex1); acc6(acc + 18, w12.y, w12.z, w12.w, ex1);
    }
    if (k < deg) {
        unsigned long long p0 = g_edge[start + k];
        float ex0 = __uint_as_float((unsigned)p0);
        int s0 = (int)(p0 >> 32);
        const uint4* h0 = H + s0 * 6 + hb;
        uint4 w00 = h0[0], w01 = h0[1], w02 = h0[2];
        den += ex0;
        acc6(acc +  0, w00.x, w00.y, w00.z, ex0); acc6(acc +  6, w00.w, w01.x, w01.y, ex0);
        acc6(acc + 12, w01.z, w01.w, w02.x, ex0); acc6(acc + 18, w02.y, w02.z, w02.w, ex0);
    }

    float inv = (deg > 0) ? 1.0f / den : 0.0f;
    float4* op = (float4*)(out + (size_t)n * OUT_F + t * 24);
#pragma unroll
    for (int i = 0; i < 6; i++)
        op[i] = make_float4(acc[4 * i] * inv, acc[4 * i + 1] * inv,
                            acc[4 * i + 2] * inv, acc[4 * i + 3] * inv);

    // Restore zero-invariants for the next graph replay (warp-safe: the
    // g_cnt load above is issued for the whole warp before any lane stores).
    if (t == 0) g_cnt[n] = 0;
    if (t == 1 && n < NBLK_SCAN) g_state[n] = 0ULL;
}

// ---------------------------------------------------------------------------
extern "C" void kernel_launch(void* const* d_in, const int* in_sizes, int n_in,
                              void* d_out, int out_size)
{
    const float* feat  = (const float*)d_in[0];
    const float* Ww    = (const float*)d_in[1];
    const float* Wb    = (const float*)d_in[2];
    const float* attnw = (const float*)d_in[3];
    const float* attnb = (const float*)d_in[4];
    const int*   src   = (const int*)d_in[5];
    const int*   dst   = (const int*)d_in[6];
    float* out = (float*)d_out;

    k_gemm<<<(N_NODES + 255) / 256, 128>>>(feat, Ww, Wb, attnw, dst);
    k_scan<<<NBLK_SCAN, 1024>>>();
    k_scatter<<<(N_EDGES / 2 + 255) / 256, 256>>>(src, dst, attnb);
    k_gather<<<(N_NODES * 2 + 255) / 256, 256>>>(out);
}

// round 5
// speedup vs baseline: 1.0278x; 1.0278x over previous
#include <cuda_runtime.h>
#include <cuda_fp16.h>
#include <cuda_bf16.h>

#define N_NODES 100000
#define N_EDGES 1600000
#define IN_F 128
#define OUT_F 48
#define H_PAD 64   // fp16 elems per padded h row (128 bytes = 1 cache line)
#define NBLK_SCAN ((N_NODES + 1023) / 1024)   // 98

// Scratch (__device__ globals; zero-initialized at load; no allocations allowed)
__device__ float  g_ssrc[N_NODES];                    // h . w_src
__device__ float  g_sdst[N_NODES];                    // h . w_dst
__device__ __half g_hh[(size_t)N_NODES * H_PAD];      // projected features (fp16, 128B rows)
__device__ int    g_cnt[N_NODES];                     // degree by dst (zero at entry!)
__device__ int    g_off[N_NODES];                     // CSR offsets
__device__ int    g_cursor[N_NODES];                  // scatter cursors
__device__ unsigned long long g_state[NBLK_SCAN];     // lookback state (zero at entry!)
__device__ unsigned long long g_edge[N_EDGES];        // packed {src, ex}

// ---------------------------------------------------------------------------
// GEMM + dst histogram.
// ---------------------------------------------------------------------------
__global__ void __launch_bounds__(128) k_gemm(
    const float* __restrict__ feat, const float* __restrict__ Ww,
    const float* __restrict__ Wb, const float* __restrict__ attnw,
    const int* __restrict__ dst)
{
    // --- histogram of dst (grid-stride, no-return atomics drain under FMAs) ---
    {
        int gsz = gridDim.x * 128;
        for (int e = blockIdx.x * 128 + threadIdx.x; e < N_EDGES; e += gsz)
            atomicAdd(&g_cnt[dst[e]], 1);
    }

    __shared__ unsigned long long sWp[IN_F][OUT_F / 2];
    __shared__ float sb[OUT_F], sws[OUT_F], swd[OUT_F];

    int tid = threadIdx.x;
    for (int i = tid; i < IN_F * (OUT_F / 2); i += 128) {
        int k  = i / (OUT_F / 2);
        int jj = i % (OUT_F / 2);
        float lo = Ww[(2 * jj) * IN_F + k];
        float hi = Ww[(2 * jj + 1) * IN_F + k];
        unsigned long long p;
        asm("mov.b64 %0, {%1, %2};" : "=l"(p) : "f"(lo), "f"(hi));
        sWp[k][jj] = p;
    }
    if (tid < OUT_F) {
        sb[tid]  = Wb[tid];
        sws[tid] = attnw[tid];
        swd[tid] = attnw[OUT_F + tid];
    }
    __syncthreads();

    long n0 = (long)blockIdx.x * 256 + tid;
    long n1 = n0 + 128;
    bool v0 = n0 < N_NODES, v1 = n1 < N_NODES;
    const float4* r0 = (const float4*)(feat + (v0 ? n0 : 0) * IN_F);
    const float4* r1 = (const float4*)(feat + (v1 ? n1 : 0) * IN_F);

    unsigned long long a0[OUT_F / 2], a1[OUT_F / 2];
#pragma unroll
    for (int jj = 0; jj < OUT_F / 2; jj++) {
        unsigned long long p;
        asm("mov.b64 %0, {%1, %2};" : "=l"(p) : "f"(sb[2 * jj]), "f"(sb[2 * jj + 1]));
        a0[jj] = p;
        a1[jj] = p;
    }

#pragma unroll 2
    for (int k4 = 0; k4 < IN_F / 4; k4++) {
        float4 f0 = r0[k4];
        float4 f1 = r1[k4];
        float fs0[4] = {f0.x, f0.y, f0.z, f0.w};
        float fs1[4] = {f1.x, f1.y, f1.z, f1.w};
#pragma unroll
        for (int u = 0; u < 4; u++) {
            unsigned long long ff0, ff1;
            asm("mov.b64 %0, {%1, %1};" : "=l"(ff0) : "f"(fs0[u]));
            asm("mov.b64 %0, {%1, %1};" : "=l"(ff1) : "f"(fs1[u]));
            int k = 4 * k4 + u;
#pragma unroll
            for (int jj = 0; jj < OUT_F / 2; jj++) {
                unsigned long long w = sWp[k][jj];
                asm("fma.rn.f32x2 %0, %1, %2, %0;" : "+l"(a0[jj]) : "l"(ff0), "l"(w));
                asm("fma.rn.f32x2 %0, %1, %2, %0;" : "+l"(a1[jj]) : "l"(ff1), "l"(w));
            }
        }
    }

    if (v0) {
        float s1 = 0.0f, s2 = 0.0f;
        unsigned hh[OUT_F / 2];
#pragma unroll
        for (int jj = 0; jj < OUT_F / 2; jj++) {
            float lo, hi;
            asm("mov.b64 {%0, %1}, %2;" : "=f"(lo), "=f"(hi) : "l"(a0[jj]));
            s1 += lo * sws[2 * jj] + hi * sws[2 * jj + 1];
            s2 += lo * swd[2 * jj] + hi * swd[2 * jj + 1];
            __half2 h2 = __floats2half2_rn(lo, hi);
            hh[jj] = *(unsigned*)&h2;
        }
        uint4* hr = (uint4*)(g_hh + (size_t)n0 * H_PAD);
#pragma unroll
        for (int i = 0; i < 6; i++)
            hr[i] = make_uint4(hh[4 * i], hh[4 * i + 1], hh[4 * i + 2], hh[4 * i + 3]);
        hr[6] = make_uint4(0, 0, 0, 0);
        hr[7] = make_uint4(0, 0, 0, 0);
        g_ssrc[n0] = s1;
        g_sdst[n0] = s2;
    }
    if (v1) {
        float s1 = 0.0f, s2 = 0.0f;
        unsigned hh[OUT_F / 2];
#pragma unroll
        for (int jj = 0; jj < OUT_F / 2; jj++) {
            float lo, hi;
            asm("mov.b64 {%0, %1}, %2;" : "=f"(lo), "=f"(hi) : "l"(a1[jj]));
            s1 += lo * sws[2 * jj] + hi * sws[2 * jj + 1];
            s2 += lo * swd[2 * jj] + hi * swd[2 * jj + 1];
            __half2 h2 = __floats2half2_rn(lo, hi);
            hh[jj] = *(unsigned*)&h2;
        }
        uint4* hr = (uint4*)(g_hh + (size_t)n1 * H_PAD);
#pragma unroll
        for (int i = 0; i < 6; i++)
            hr[i] = make_uint4(hh[4 * i], hh[4 * i + 1], hh[4 * i + 2], hh[4 * i + 3]);
        hr[6] = make_uint4(0, 0, 0, 0);
        hr[7] = make_uint4(0, 0, 0, 0);
        g_ssrc[n1] = s1;
        g_sdst[n1] = s2;
    }
}

// ---------------------------------------------------------------------------
// Single-pass exclusive scan of g_cnt -> g_off/g_cursor (decoupled lookback).
// ---------------------------------------------------------------------------
__global__ void __launch_bounds__(1024) k_scan()
{
    __shared__ int wsum[32];
    __shared__ int s_prefix;
    int tid = threadIdx.x, bid = blockIdx.x;
    int gid = bid * 1024 + tid;
    int lane = tid & 31, wid = tid >> 5;
    int x = (gid < N_NODES) ? g_cnt[gid] : 0;
    int incl = x;
#pragma unroll
    for (int o = 1; o < 32; o <<= 1) {
        int y = __shfl_up_sync(0xFFFFFFFFu, incl, o);
        if (lane >= o) incl += y;
    }
    if (lane == 31) wsum[wid] = incl;
    __syncthreads();
    if (wid == 0) {
        int v = wsum[lane];
#pragma unroll
        for (int o = 1; o < 32; o <<= 1) {
            int y = __shfl_up_sync(0xFFFFFFFFu, v, o);
            if (lane >= o) v += y;
        }
        wsum[lane] = v;
    }
    __syncthreads();
    int wofs = (wid > 0) ? wsum[wid - 1] : 0;
    int total = wsum[31];

    if (tid == 0) {
        if (bid == 0) {
            atomicExch(&g_state[0], (2ULL << 62) | (unsigned)total);
            s_prefix = 0;
        } else {
            atomicExch(&g_state[bid], (1ULL << 62) | (unsigned)total);
            int run = 0;
            int j = bid - 1;
            while (true) {
                unsigned long long v = atomicAdd(&g_state[j], 0ULL);
                unsigned f = (unsigned)(v >> 62);
                if (f == 0) { __nanosleep(20); continue; }
                run += (int)(v & 0xFFFFFFFFULL);
                if (f == 2) break;
                j--;
            }
            atomicExch(&g_state[bid], (2ULL << 62) | (unsigned)(run + total));
            s_prefix = run;
        }
    }
    __syncthreads();
    if (gid < N_NODES) {
        int o = s_prefix + wofs + incl - x;
        g_off[gid] = o;
        g_cursor[gid] = o;
    }
}

// ---------------------------------------------------------------------------
// Scatter: 2 edges/thread; ex = exp(leaky(s_src[s]+s_dst[d]+b));
// place {src,ex} at dst-sorted position.
// ---------------------------------------------------------------------------
__global__ void __launch_bounds__(256) k_scatter(
    const int* __restrict__ src, const int* __restrict__ dst,
    const float* __restrict__ attnb)
{
    int i = blockIdx.x * blockDim.x + threadIdx.x;
    int e0 = i * 2;
    if (e0 >= N_EDGES) return;
    float b = attnb[0];

    int2 s2 = *(const int2*)(src + e0);
    int2 d2 = *(const int2*)(dst + e0);

    float v0 = g_ssrc[s2.x] + g_sdst[d2.x] + b;
    float v1 = g_ssrc[s2.y] + g_sdst[d2.y] + b;
    v0 = (v0 > 0.0f) ? v0 : 0.2f * v0;
    v1 = (v1 > 0.0f) ? v1 : 0.2f * v1;
    float ex0 = __expf(v0);
    float ex1 = __expf(v1);

    int p0 = atomicAdd(&g_cursor[d2.x], 1);
    int p1 = atomicAdd(&g_cursor[d2.y], 1);
    g_edge[p0] = ((unsigned long long)(unsigned)s2.x << 32) | __float_as_uint(ex0);
    g_edge[p1] = ((unsigned long long)(unsigned)s2.y << 32) | __float_as_uint(ex1);
}

// ---------------------------------------------------------------------------
// Gather: 8 threads/node; lane t loads uint4 #t of the padded 128B h row --
// one cache line per edge per node-group, fully coalesced. Lanes 0-5 own 8
// outputs each; lanes 6-7 accumulate pad zeros and do invariant restores.
// ---------------------------------------------------------------------------
__device__ __forceinline__ void acc8(float* a, uint4 w, float ex)
{
    float2 f;
    f = __half22float2(*(__half2*)&w.x); a[0] = fmaf(f.x, ex, a[0]); a[1] = fmaf(f.y, ex, a[1]);
    f = __half22float2(*(__half2*)&w.y); a[2] = fmaf(f.x, ex, a[2]); a[3] = fmaf(f.y, ex, a[3]);
    f = __half22float2(*(__half2*)&w.z); a[4] = fmaf(f.x, ex, a[4]); a[5] = fmaf(f.y, ex, a[5]);
    f = __half22float2(*(__half2*)&w.w); a[6] = fmaf(f.x, ex, a[6]); a[7] = fmaf(f.y, ex, a[7]);
}

__global__ void __launch_bounds__(256) k_gather(float* __restrict__ out)
{
    int gt = blockIdx.x * blockDim.x + threadIdx.x;
    int n = gt >> 3;
    int t = gt & 7;
    if (n >= N_NODES) return;
    int start = g_off[n];
    int deg = g_cnt[n];

    const uint4* H = (const uint4*)g_hh;  // padded row = 8 uint4 (128B)

    float acc[8];
#pragma unroll
    for (int i = 0; i < 8; i++) acc[i] = 0.0f;
    float den = 0.0f;

    int k = 0;
    for (; k + 2 <= deg; k += 2) {
        unsigned long long p0 = g_edge[start + k];
        unsigned long long p1 = g_edge[start + k + 1];
        float ex0 = __uint_as_float((unsigned)p0);
        float ex1 = __uint_as_float((unsigned)p1);
        int s0 = (int)(p0 >> 32), s1 = (int)(p1 >> 32);
        uint4 w0 = H[s0 * 8 + t];
        uint4 w1 = H[s1 * 8 + t];
        den += ex0 + ex1;
        acc8(acc, w0, ex0);
        acc8(acc, w1, ex1);
    }
    if (k < deg) {
        unsigned long long p0 = g_edge[start + k];
        float ex0 = __uint_as_float((unsigned)p0);
        int s0 = (int)(p0 >> 32);
        uint4 w0 = H[s0 * 8 + t];
        den += ex0;
        acc8(acc, w0, ex0);
    }

    if (t < 6) {
        float inv = (deg > 0) ? 1.0f / den : 0.0f;
        float4* op = (float4*)(out + (size_t)n * OUT_F + t * 8);
        op[0] = make_float4(acc[0] * inv, acc[1] * inv, acc[2] * inv, acc[3] * inv);
        op[1] = make_float4(acc[4] * inv, acc[5] * inv, acc[6] * inv, acc[7] * inv);
    }
    // Restore zero-invariants for the next graph replay (warp-safe: the
    // g_cnt load above is issued for the whole warp before any lane stores).
    if (t == 6) g_cnt[n] = 0;
    if (t == 7 && n < NBLK_SCAN) g_state[n] = 0ULL;
}

// ---------------------------------------------------------------------------
extern "C" void kernel_launch(void* const* d_in, const int* in_sizes, int n_in,
                              void* d_out, int out_size)
{
    const float* feat  = (const float*)d_in[0];
    const float* Ww    = (const float*)d_in[1];
    const float* Wb    = (const float*)d_in[2];
    const float* attnw = (const float*)d_in[3];
    const float* attnb = (const float*)d_in[4];
    const int*   src   = (const int*)d_in[5];
    const int*   dst   = (const int*)d_in[6];
    float* out = (float*)d_out;

    k_gemm<<<(N_NODES + 255) / 256, 128>>>(feat, Ww, Wb, attnw, dst);
    k_scan<<<NBLK_SCAN, 1024>>>();
    k_scatter<<<(N_EDGES / 2 + 255) / 256, 256>>>(src, dst, attnb);
    k_gather<<<(N_NODES * 8 + 255) / 256, 256>>>(out);
}